// round 9
// baseline (speedup 1.0000x reference)
#include <cuda_runtime.h>
#include <cuda_bf16.h>
#include <cstdint>

#define N_NODES 100000
#define D 128
#define N_EDGES 1600000
#define TILE 32
#define NTILES (N_NODES / TILE)      // 3125 exact
#define CAP 128
#define NB_Z ((N_NODES + 255) / 256)

__device__ int g_cnt[N_NODES];
__device__ int g_esrc[(size_t)N_NODES * CAP];   // 51.2 MB bucketed edge slots
__device__ int g_is64;

// ---------------- helpers ----------------
__device__ __forceinline__ uint32_t prmt(uint32_t a, uint32_t b, uint32_t s) {
    uint32_t d;
    asm("prmt.b32 %0, %1, %2, %3;" : "=r"(d) : "r"(a), "r"(b), "r"(s));
    return d;
}
// pack (bf16(x - bf16(x)) << 16) | bf16(x)
__device__ __forceinline__ uint32_t pack_split(float x) {
    float ah = __bfloat162float(__float2bfloat16_rn(x));
    uint32_t r;
    asm("cvt.rn.bf16x2.f32 %0, %1, %2;" : "=r"(r) : "f"(x - ah), "f"(ah));
    return r;
}
__device__ __forceinline__ void mma_bf16(float d[4], const uint32_t a[4],
                                         const uint32_t b[2]) {
    asm volatile(
        "mma.sync.aligned.m16n8k16.row.col.f32.bf16.bf16.f32 "
        "{%0,%1,%2,%3}, {%4,%5,%6,%7}, {%8,%9}, {%0,%1,%2,%3};"
        : "+f"(d[0]), "+f"(d[1]), "+f"(d[2]), "+f"(d[3])
        : "r"(a[0]), "r"(a[1]), "r"(a[2]), "r"(a[3]), "r"(b[0]), "r"(b[1]));
}
__device__ __forceinline__ void load_edge(const void* src_raw, const void* dst_raw,
                                          int e, int is64, int& s, int& d) {
    if (is64) {
        s = (int)((const long long*)src_raw)[e];
        d = (int)((const long long*)dst_raw)[e];
    } else {
        s = ((const int*)src_raw)[e];
        d = ((const int*)dst_raw)[e];
    }
}

// ---------------- kernel 1: zero counts + dtype sniff ----------------
__global__ void zero_sniff_kernel(const void* __restrict__ src) {
    int i = blockIdx.x * blockDim.x + threadIdx.x;
    if (i < N_NODES) g_cnt[i] = 0;
    if (i == 0) {
        const long long* p = (const long long*)src;
        int ok = 1;
        #pragma unroll 1
        for (int q = 0; q < 64; q++) {
            long long v = p[q];
            if (v < 0 || v >= N_NODES) { ok = 0; break; }
        }
        g_is64 = ok;
    }
}

// ---------------- kernel 2: bucketed edge fill (no scan needed) ----------------
__global__ void fill_kernel(const void* __restrict__ src_raw,
                            const void* __restrict__ dst_raw) {
    const int is64 = g_is64;
    int idx = blockIdx.x * blockDim.x + threadIdx.x;
    int stride = gridDim.x * blockDim.x;
    for (int e = idx; e < N_EDGES; e += stride) {
        int s, d;
        load_edge(src_raw, dst_raw, e, is64, s, d);
        if ((unsigned)s < N_NODES && (unsigned)d < N_NODES) {
            int pos = atomicAdd(&g_cnt[d], 1);
            if (pos < CAP) g_esrc[(size_t)d * CAP + pos] = s;
        }
    }
}

// ---------------- fused kernel: gather + bf16-split mma GEMM ----------------
// SMEM (uint32 words): sB[32768] = W' packed-split frag-linear (built once),
//                      sX[2][8192] = X tiles (self k<128 | neigh k>=128).
// Fragment-linear layout, per (ks, rb 16-row block) region of 256 words:
//   half h (rows g / g+8), thread t=(g*4+p): words [t*4+c] ^ ((ks&7)*4),
//   c: 0,1 = elems k0,k0+1 (k0=p*2); c: 2,3 = elems k0+8,k0+9.
// Each packed word = (al<<16)|ah (bf16 split). Compute: LDS.128 + PRMT -> mma.
__global__ __launch_bounds__(384, 1)
void fused_kernel(const float* __restrict__ h,
                  const float* __restrict__ Ws,
                  const float* __restrict__ Wn,
                  float* __restrict__ out) {
    extern __shared__ uint32_t smw[];
    uint32_t* sB = smw;            // 32768 words (128 KB)
    uint32_t* sX = smw + 32768;    // 2 x 8192 words (64 KB)

    int tid = threadIdx.x, wid = tid >> 5, lane = tid & 31;
    const bool is_gather = (wid >= 4);

    // ---- gather: CSR-bucket mean + self, packed-split into frag layout ----
    auto fill_tile = [&](int tile, int buf) {
        uint32_t* bX = sX + buf * 8192;
        int gwid = wid - 4;                 // 0..7
        int ks_s = lane >> 2, j = lane & 3;
        int sw = (ks_s & 7) * 4;
        int p0 = (j & 1) * 2, cb = (j >> 1) * 2;
        #pragma unroll 1
        for (int rr4 = 0; rr4 < 4; rr4++) {
            int r = gwid * 4 + rr4;
            int row = tile * TILE + r;
            int rb = r >> 4, rr = r & 15;
            int half = rr >> 3, g = rr & 7;
            int off0 = (((g * 4 + p0) * 4 + cb) ^ sw) + half * 128;
            int off1 = (((g * 4 + p0 + 1) * 4 + cb) ^ sw) + half * 128;
            uint32_t* base_s = bX + (ks_s * 2 + rb) * 256;
            uint32_t* base_n = bX + ((ks_s + 8) * 2 + rb) * 256;

            float4 self = reinterpret_cast<const float4*>(h + (size_t)row * D)[lane];
            int deg = g_cnt[row];
            float inv = 1.0f / fmaxf((float)deg, 1.0f);
            int nd = deg < CAP ? deg : CAP;
            const int* el = g_esrc + (size_t)row * CAP;
            float4 acc = make_float4(0.f, 0.f, 0.f, 0.f);
            int e = 0;
            #pragma unroll 1
            for (; e + 8 <= nd; e += 8) {
                int si[8];
                #pragma unroll
                for (int q = 0; q < 8; q++) si[q] = el[e + q];
                float4 v[8];
                #pragma unroll
                for (int q = 0; q < 8; q++)
                    v[q] = reinterpret_cast<const float4*>(h + (size_t)si[q] * D)[lane];
                #pragma unroll
                for (int q = 0; q < 8; q++) {
                    acc.x += v[q].x; acc.y += v[q].y;
                    acc.z += v[q].z; acc.w += v[q].w;
                }
            }
            #pragma unroll 1
            for (; e < nd; e++) {
                float4 v0 = reinterpret_cast<const float4*>(h + (size_t)el[e] * D)[lane];
                acc.x += v0.x; acc.y += v0.y; acc.z += v0.z; acc.w += v0.w;
            }
            acc.x *= inv; acc.y *= inv; acc.z *= inv; acc.w *= inv;

            *reinterpret_cast<uint2*>(base_s + off0) =
                make_uint2(pack_split(self.x), pack_split(self.y));
            *reinterpret_cast<uint2*>(base_s + off1) =
                make_uint2(pack_split(self.z), pack_split(self.w));
            *reinterpret_cast<uint2*>(base_n + off0) =
                make_uint2(pack_split(acc.x), pack_split(acc.y));
            *reinterpret_cast<uint2*>(base_n + off1) =
                make_uint2(pack_split(acc.z), pack_split(acc.w));
        }
    };

    // ---- prologue: compute warps build packed-split B; gather fills buf0 ----
    int t0 = blockIdx.x;
    if (is_gather) {
        if (t0 < NTILES) fill_tile(t0, 0);
    } else {
        for (int idx = tid; idx < 32768; idx += 128) {
            int k = idx >> 7, n = idx & 127;
            float w = (k < 128) ? Ws[k * 128 + n] : Wn[(k - 128) * 128 + n];
            int ks = k >> 4, kin = k & 15, nb = n >> 3, g = n & 7;
            int p = (kin & 7) >> 1;
            int c = (kin & 1) + ((kin & 8) ? 2 : 0);
            int word = (ks * 16 + nb) * 128 + ((((g * 4 + p) * 4) + c) ^ ((ks & 7) * 4));
            sB[word] = pack_split(w);
        }
    }
    __syncthreads();

    int p = 0;
    const int nbg0 = wid * 4;   // compute warp w owns cols w*32..w*32+31

    for (int t = t0; t < NTILES; t += gridDim.x) {
        if (is_gather) {
            int tn = t + gridDim.x;
            if (tn < NTILES) fill_tile(tn, p ^ 1);
        } else {
            uint32_t* bX = sX + p * 8192;
            float dd[2][4][4];
            #pragma unroll
            for (int rb = 0; rb < 2; rb++)
                #pragma unroll
                for (int nb = 0; nb < 4; nb++)
                    #pragma unroll
                    for (int q = 0; q < 4; q++) dd[rb][nb][q] = 0.f;

            #pragma unroll 1
            for (int ks = 0; ks < 16; ks++) {
                const int sw = (ks & 7) * 4;
                const int lsw = (lane * 4) ^ sw;
                uint32_t ah[2][4], al[2][4];
                #pragma unroll
                for (int rb = 0; rb < 2; rb++) {
                    const uint32_t* reg = bX + (ks * 2 + rb) * 256;
                    uint4 lo = *reinterpret_cast<const uint4*>(reg + lsw);
                    uint4 hi = *reinterpret_cast<const uint4*>(reg + 128 + lsw);
                    ah[rb][0] = prmt(lo.x, lo.y, 0x5410);
                    al[rb][0] = prmt(lo.x, lo.y, 0x7632);
                    ah[rb][2] = prmt(lo.z, lo.w, 0x5410);
                    al[rb][2] = prmt(lo.z, lo.w, 0x7632);
                    ah[rb][1] = prmt(hi.x, hi.y, 0x5410);
                    al[rb][1] = prmt(hi.x, hi.y, 0x7632);
                    ah[rb][3] = prmt(hi.z, hi.w, 0x5410);
                    al[rb][3] = prmt(hi.z, hi.w, 0x7632);
                }
                #pragma unroll
                for (int nb = 0; nb < 4; nb++) {
                    const uint32_t* regb = sB + (ks * 16 + nbg0 + nb) * 128;
                    uint4 bw = *reinterpret_cast<const uint4*>(regb + lsw);
                    uint32_t bh[2], bl[2];
                    bh[0] = prmt(bw.x, bw.y, 0x5410);
                    bl[0] = prmt(bw.x, bw.y, 0x7632);
                    bh[1] = prmt(bw.z, bw.w, 0x5410);
                    bl[1] = prmt(bw.z, bw.w, 0x7632);
                    #pragma unroll
                    for (int rb = 0; rb < 2; rb++) {
                        mma_bf16(dd[rb][nb], ah[rb], bh);
                        mma_bf16(dd[rb][nb], al[rb], bh);
                        mma_bf16(dd[rb][nb], ah[rb], bl);
                    }
                }
            }

            // epilogue: D frag (m16n8) -> gmem
            int rbase = t * TILE;
            #pragma unroll
            for (int rb = 0; rb < 2; rb++) {
                int r0 = rbase + rb * 16 + (lane >> 2);
                #pragma unroll
                for (int nb = 0; nb < 4; nb++) {
                    int c0 = (nbg0 + nb) * 8 + (lane & 3) * 2;
                    *reinterpret_cast<float2*>(out + (size_t)r0 * D + c0) =
                        make_float2(dd[rb][nb][0], dd[rb][nb][1]);
                    *reinterpret_cast<float2*>(out + (size_t)(r0 + 8) * D + c0) =
                        make_float2(dd[rb][nb][2], dd[rb][nb][3]);
                }
            }
        }
        __syncthreads();
        p ^= 1;
    }
}

// ---------------- launch ----------------
extern "C" void kernel_launch(void* const* d_in, const int* in_sizes, int n_in,
                              void* d_out, int out_size) {
    const float* h      = (const float*)d_in[0];
    const void*  src    = d_in[1];
    const void*  dst    = d_in[2];
    const float* Wself  = (const float*)d_in[3];
    const float* Wneigh = (const float*)d_in[4];
    float*       out    = (float*)d_out;

    static bool attr_set = false;
    if (!attr_set) {
        cudaFuncSetAttribute(fused_kernel,
                             cudaFuncAttributeMaxDynamicSharedMemorySize,
                             196608);
        attr_set = true;
    }

    zero_sniff_kernel<<<NB_Z, 256>>>(src);
    fill_kernel<<<2048, 256>>>(src, dst);
    fused_kernel<<<152, 384, 196608>>>(h, Wself, Wneigh, out);
}